// round 10
// baseline (speedup 1.0000x reference)
#include <cuda_runtime.h>
#include <cstdint>

#define NN   100000
#define NE   3200000
#define INF  1433
#define HID  16
#define OUTF 7
#define SCAN_BLK 512
#define NSCAN ((NN + SCAN_BLK - 1) / SCAN_BLK)   // 196

typedef unsigned long long ull;

// ---- scratch (device globals: allocation-free) ----
__device__ int   g_idx64;               // 1 if edge_index is int64, 0 if int32
__device__ int   g_idx[2 * NE];         // densified edge indices: [src | dst]
__device__ int   g_csr[NE];             // src ids sorted by dst
__device__ int   g_cnt_src[NN];         // out-degree
__device__ int   g_cnt_dst[NN];         // in-degree
__device__ int   g_off[NN];             // CSR row offsets (by dst)
__device__ int   g_cur[NN];             // fill cursors
__device__ int   g_bsum[NSCAN];         // scan block sums
__device__ float g_ns[NN];
__device__ float g_nd[NN];
__device__ float g_x1[(size_t)NN * HID];   // RAW feat@W1 (ns applied in gather1)
__device__ float g_m1[(size_t)NN * HID];   // gathered layer-1 messages
__device__ float g_x2[(size_t)NN * 8];     // (relu(h)*ns)@W2, padded to 8

// ---- streams/events for capture-fork (created before harness checkpoints) ----
struct HxInit {
    cudaStream_t s2;
    cudaEvent_t  e0, e1;
    HxInit() {
        cudaStreamCreateWithFlags(&s2, cudaStreamNonBlocking);
        cudaEventCreateWithFlags(&e0, cudaEventDisableTiming);
        cudaEventCreateWithFlags(&e1, cudaEventDisableTiming);
    }
};
static HxInit g_hx;

// ---------------------------------------------------------------------------
__global__ void k_detect(const unsigned int* __restrict__ ei_words) {
    __shared__ unsigned int acc;
    if (threadIdx.x == 0) acc = 0u;
    __syncthreads();
    unsigned int v = ei_words[2 * threadIdx.x + 1];
    atomicOr(&acc, v);
    __syncthreads();
    if (threadIdx.x == 0) g_idx64 = (acc == 0u) ? 1 : 0;
}

__global__ void k_zero() {
    int i = blockIdx.x * blockDim.x + threadIdx.x;
    if (i < NN) { g_cnt_src[i] = 0; g_cnt_dst[i] = 0; }
}

// fused convert + degree count
__global__ void k_convcnt(const void* __restrict__ ei) {
    int e = blockIdx.x * blockDim.x + threadIdx.x;
    if (e >= NE) return;
    int s, d;
    if (g_idx64) {
        s = (int)((const long long*)ei)[e];
        d = (int)((const long long*)ei)[(size_t)NE + e];
    } else {
        s = ((const int*)ei)[e];
        d = ((const int*)ei)[NE + e];
    }
    g_idx[e] = s;
    g_idx[NE + e] = d;
    atomicAdd(&g_cnt_src[s], 1);
    atomicAdd(&g_cnt_dst[d], 1);
}

__global__ void k_norm() {
    int i = blockIdx.x * blockDim.x + threadIdx.x;
    if (i >= NN) return;
    g_ns[i] = rsqrtf(fmaxf((float)g_cnt_src[i], 1.0f));
    g_nd[i] = rsqrtf(fmaxf((float)g_cnt_dst[i], 1.0f));
}

// exclusive scan of g_cnt_dst -> g_off
__global__ void k_scan1() {
    __shared__ int s[SCAN_BLK];
    int tid = threadIdx.x;
    int i = blockIdx.x * SCAN_BLK + tid;
    int v = (i < NN) ? g_cnt_dst[i] : 0;
    s[tid] = v;
    __syncthreads();
    for (int o = 1; o < SCAN_BLK; o <<= 1) {
        int t = (tid >= o) ? s[tid - o] : 0;
        __syncthreads();
        s[tid] += t;
        __syncthreads();
    }
    if (i < NN) g_off[i] = s[tid] - v;
    if (tid == SCAN_BLK - 1) g_bsum[blockIdx.x] = s[tid];
}

__global__ void k_scan2() {
    __shared__ int s[SCAN_BLK];
    int tid = threadIdx.x;
    int v = (tid < NSCAN) ? g_bsum[tid] : 0;
    s[tid] = v;
    __syncthreads();
    for (int o = 1; o < SCAN_BLK; o <<= 1) {
        int t = (tid >= o) ? s[tid - o] : 0;
        __syncthreads();
        s[tid] += t;
        __syncthreads();
    }
    if (tid < NSCAN) g_bsum[tid] = s[tid] - v;
}

__global__ void k_scan3() {
    int i = blockIdx.x * SCAN_BLK + threadIdx.x;
    if (i >= NN) return;
    int o = g_off[i] + g_bsum[blockIdx.x];
    g_off[i] = o;
    g_cur[i] = o;
}

__global__ void k_fill() {
    int e = blockIdx.x * blockDim.x + threadIdx.x;
    if (e >= NE) return;
    int s = g_idx[e];
    int d = g_idx[NE + e];
    int pos = atomicAdd(&g_cur[d], 1);
    g_csr[pos] = s;
}

// ---------------------------------------------------------------------------
// gemm1: x1_raw = feat @ W1   [NN,1433] x [1433,16]
// Block = 4 warps, each warp autonomous (NO __syncthreads): warp owns 64 rows
// as two 32-row tiles; per-warp W tile (16B-aligned, lane copies one W row
// via float4). Inner kk: 2 LDS.32 (f) + 4 LDS.128 (w broadcast) + 16 FFMA2.
// Row tail clamped + guarded stores; K tail zero-filled / clamped.
// ---------------------------------------------------------------------------
__global__ void __launch_bounds__(128) k_gemm1(const float* __restrict__ feat,
                                               const float* __restrict__ W1) {
    __shared__ float tA[4][32][33];
    __shared__ float tB[4][32][33];
    __shared__ __align__(16) float sW[4][32][16];
    const int warp = threadIdx.x >> 5;
    const int lane = threadIdx.x & 31;
    const int r0 = (blockIdx.x * 4 + warp) * 64;

    ull acc0[8], acc1[8];
#pragma unroll
    for (int j = 0; j < 8; j++) { acc0[j] = 0ULL; acc1[j] = 0ULL; }

    float (*a)[33] = tA[warp];
    float (*b)[33] = tB[warp];
    float (*w)[16] = sW[warp];

    for (int k0 = 0; k0 < INF; k0 += 32) {
        const int k = k0 + lane;
        const bool kok = (k < INF);
        __syncwarp();   // WAR: previous iteration's reads done before restage
        // stage feature tiles (coalesced over k; rows clamped for grid tail)
#pragma unroll 8
        for (int rr = 0; rr < 32; rr++)
            a[rr][lane] = kok ? feat[(size_t)min(r0 + rr, NN - 1) * INF + k] : 0.f;
#pragma unroll 8
        for (int rr = 0; rr < 32; rr++)
            b[rr][lane] = kok ? feat[(size_t)min(r0 + 32 + rr, NN - 1) * INF + k] : 0.f;
        // stage W tile: lane copies W row (k0+lane), clamped (f=0 covers tail)
        {
            const float4* src = (const float4*)(W1 + (size_t)min(k, INF - 1) * 16);
            float4* dst = (float4*)w[lane];
            dst[0] = src[0]; dst[1] = src[1]; dst[2] = src[2]; dst[3] = src[3];
        }
        __syncwarp();

#pragma unroll 8
        for (int kk = 0; kk < 32; kk++) {
            const float f0 = a[lane][kk];          // conflict-free (pad 33)
            const float f1 = b[lane][kk];
            ull ff0, ff1;
            asm("mov.b64 %0, {%1, %1};" : "=l"(ff0) : "f"(f0));
            asm("mov.b64 %0, {%1, %1};" : "=l"(ff1) : "f"(f1));
            const ulonglong2* wp = (const ulonglong2*)w[kk];   // broadcast
            const ulonglong2 p0 = wp[0], p1 = wp[1], p2 = wp[2], p3 = wp[3];
            asm("fma.rn.f32x2 %0, %1, %2, %0;" : "+l"(acc0[0]) : "l"(ff0), "l"(p0.x));
            asm("fma.rn.f32x2 %0, %1, %2, %0;" : "+l"(acc0[1]) : "l"(ff0), "l"(p0.y));
            asm("fma.rn.f32x2 %0, %1, %2, %0;" : "+l"(acc0[2]) : "l"(ff0), "l"(p1.x));
            asm("fma.rn.f32x2 %0, %1, %2, %0;" : "+l"(acc0[3]) : "l"(ff0), "l"(p1.y));
            asm("fma.rn.f32x2 %0, %1, %2, %0;" : "+l"(acc0[4]) : "l"(ff0), "l"(p2.x));
            asm("fma.rn.f32x2 %0, %1, %2, %0;" : "+l"(acc0[5]) : "l"(ff0), "l"(p2.y));
            asm("fma.rn.f32x2 %0, %1, %2, %0;" : "+l"(acc0[6]) : "l"(ff0), "l"(p3.x));
            asm("fma.rn.f32x2 %0, %1, %2, %0;" : "+l"(acc0[7]) : "l"(ff0), "l"(p3.y));
            asm("fma.rn.f32x2 %0, %1, %2, %0;" : "+l"(acc1[0]) : "l"(ff1), "l"(p0.x));
            asm("fma.rn.f32x2 %0, %1, %2, %0;" : "+l"(acc1[1]) : "l"(ff1), "l"(p0.y));
            asm("fma.rn.f32x2 %0, %1, %2, %0;" : "+l"(acc1[2]) : "l"(ff1), "l"(p1.x));
            asm("fma.rn.f32x2 %0, %1, %2, %0;" : "+l"(acc1[3]) : "l"(ff1), "l"(p1.y));
            asm("fma.rn.f32x2 %0, %1, %2, %0;" : "+l"(acc1[4]) : "l"(ff1), "l"(p2.x));
            asm("fma.rn.f32x2 %0, %1, %2, %0;" : "+l"(acc1[5]) : "l"(ff1), "l"(p2.y));
            asm("fma.rn.f32x2 %0, %1, %2, %0;" : "+l"(acc1[6]) : "l"(ff1), "l"(p3.x));
            asm("fma.rn.f32x2 %0, %1, %2, %0;" : "+l"(acc1[7]) : "l"(ff1), "l"(p3.y));
        }
    }

    const int row0 = r0 + lane;
    const int row1 = r0 + 32 + lane;
    if (row0 < NN) {
        float4* op = (float4*)(g_x1 + (size_t)row0 * 16);
#pragma unroll
        for (int c = 0; c < 4; c++) {
            float x0, y0, x1, y1;
            asm("mov.b64 {%0, %1}, %2;" : "=f"(x0), "=f"(y0) : "l"(acc0[2 * c]));
            asm("mov.b64 {%0, %1}, %2;" : "=f"(x1), "=f"(y1) : "l"(acc0[2 * c + 1]));
            op[c] = make_float4(x0, y0, x1, y1);
        }
    }
    if (row1 < NN) {
        float4* op = (float4*)(g_x1 + (size_t)row1 * 16);
#pragma unroll
        for (int c = 0; c < 4; c++) {
            float x0, y0, x1, y1;
            asm("mov.b64 {%0, %1}, %2;" : "=f"(x0), "=f"(y0) : "l"(acc1[2 * c]));
            asm("mov.b64 {%0, %1}, %2;" : "=f"(x1), "=f"(y1) : "l"(acc1[2 * c + 1]));
            op[c] = make_float4(x0, y0, x1, y1);
        }
    }
}

// ---------------------------------------------------------------------------
// gather1: m1[n] = sum_e ns[src] * x1_raw[src]; 16 lanes per node
// ---------------------------------------------------------------------------
__global__ void __launch_bounds__(256) k_gather1() {
    int t = blockIdx.x * blockDim.x + threadIdx.x;
    int node = t >> 4;
    int j = t & 15;
    if (node >= NN) return;
    int beg = g_off[node];
    int end = beg + g_cnt_dst[node];
    float acc = 0.f;
#pragma unroll 4
    for (int e = beg; e < end; e++) {
        int s = g_csr[e];
        float nsv = g_ns[s];
        acc = fmaf(g_x1[(size_t)s * 16 + j], nsv, acc);
    }
    g_m1[(size_t)node * 16 + j] = acc;
}

// ---------------------------------------------------------------------------
// layer2: h = relu(m1*nd + b1);  x2 = (h*ns) @ W2  (pad col 7 = 0)
// ---------------------------------------------------------------------------
__global__ void __launch_bounds__(256) k_layer2(const float* __restrict__ b1,
                                                const float* __restrict__ W2) {
    __shared__ float sW[16 * 7];
    __shared__ float sb1[16];
    const int tid = threadIdx.x;
    if (tid < 112) sW[tid] = W2[tid];
    if (tid < 16)  sb1[tid] = b1[tid];
    __syncthreads();

    const int r = blockIdx.x * blockDim.x + tid;
    if (r >= NN) return;
    const float nd = g_nd[r];
    const float ns = g_ns[r];

    float h[16];
    const float4* m = (const float4*)(g_m1 + (size_t)r * 16);
#pragma unroll
    for (int c = 0; c < 4; c++) {
        const float4 v = m[c];
        h[4 * c + 0] = fmaxf(fmaf(v.x, nd, sb1[4 * c + 0]), 0.f) * ns;
        h[4 * c + 1] = fmaxf(fmaf(v.y, nd, sb1[4 * c + 1]), 0.f) * ns;
        h[4 * c + 2] = fmaxf(fmaf(v.z, nd, sb1[4 * c + 2]), 0.f) * ns;
        h[4 * c + 3] = fmaxf(fmaf(v.w, nd, sb1[4 * c + 3]), 0.f) * ns;
    }

    float* xo = g_x2 + (size_t)r * 8;
#pragma unroll
    for (int j2 = 0; j2 < 7; j2++) {
        float o = 0.f;
#pragma unroll
        for (int j = 0; j < 16; j++) o = fmaf(h[j], sW[j * 7 + j2], o);
        xo[j2] = o;
    }
    xo[7] = 0.f;
}

// ---------------------------------------------------------------------------
// gather2 + epilogue: out[n,:7] = (sum x2[src]) * nd + b2 ; 8 lanes per node
// ---------------------------------------------------------------------------
__global__ void __launch_bounds__(256) k_gather2(float* __restrict__ out,
                                                 const float* __restrict__ b2) {
    int t = blockIdx.x * blockDim.x + threadIdx.x;
    int node = t >> 3;
    int j = t & 7;
    if (node >= NN) return;
    int beg = g_off[node];
    int end = beg + g_cnt_dst[node];
    float acc = 0.f;
#pragma unroll 4
    for (int e = beg; e < end; e++) {
        int s = g_csr[e];
        acc += g_x2[(size_t)s * 8 + j];
    }
    if (j < 7)
        out[(size_t)node * 7 + j] = fmaf(acc, g_nd[node], __ldg(b2 + j));
}

// ---------------------------------------------------------------------------
extern "C" void kernel_launch(void* const* d_in, const int* in_sizes, int n_in,
                              void* d_out, int out_size) {
    const float* feat = (const float*)d_in[0];
    const void*  ei   = d_in[1];
    const float* W1   = (const float*)d_in[2];
    const float* b1   = (const float*)d_in[3];
    const float* W2   = (const float*)d_in[4];
    const float* b2   = (const float*)d_in[5];
    float*       out  = (float*)d_out;

    // fork: gemm1 (independent of edges) runs concurrent with CSR build
    cudaEventRecord(g_hx.e0, 0);
    cudaStreamWaitEvent(g_hx.s2, g_hx.e0, 0);
    k_gemm1<<<(NN + 255) / 256, 128, 0, g_hx.s2>>>(feat, W1);
    cudaEventRecord(g_hx.e1, g_hx.s2);

    // main stream: CSR build
    k_detect<<<1, 32>>>((const unsigned int*)ei);
    k_zero<<<(NN + 255) / 256, 256>>>();
    k_convcnt<<<(NE + 255) / 256, 256>>>(ei);
    k_norm<<<(NN + 255) / 256, 256>>>();
    k_scan1<<<NSCAN, SCAN_BLK>>>();
    k_scan2<<<1, SCAN_BLK>>>();
    k_scan3<<<NSCAN, SCAN_BLK>>>();
    k_fill<<<(NE + 255) / 256, 256>>>();

    // join: gather needs x1 + CSR
    cudaStreamWaitEvent(0, g_hx.e1, 0);
    k_gather1<<<(NN * 16 + 255) / 256, 256>>>();
    k_layer2<<<(NN + 255) / 256, 256>>>(b1, W2);
    k_gather2<<<(NN * 8 + 255) / 256, 256>>>(out, b2);
}